// round 1
// baseline (speedup 1.0000x reference)
#include <cuda_runtime.h>

// Problem constants (fixed by the dataset)
#define NN   200000      // nodes
#define NE   6400000     // edges
#define MM   10000       // NN/20 sampled rows
#define FIN  100
#define HD   16
#define FCAP 1048576     // capacity for filtered (dst%20==0) edges; expected ~320k

// ---------------- scratch (device globals; no allocation allowed) ----------
__device__ int      g_deg[NN];
__device__ float    g_dinv[NN];
__device__ float    g_h[NN * HD];       // x @ W1
__device__ float    g_agg1[NN * HD];    // layer-1 neighbor aggregation
__device__ float    g_h2[NN * 2];       // relu(h1) @ W2
__device__ float    g_agg2[MM * 2];     // layer-2 aggregation (sampled dst only)
__device__ float    g_bp[MM * 5];       // BP_input rows
__device__ int      g_fsrc[FCAP];
__device__ int      g_fidx[FCAP];
__device__ float    g_fnorm[FCAP];
__device__ int      g_fcnt;
__device__ unsigned g_mn, g_mx;         // encoded float min/max

// monotonic float<->uint encoding for atomicMin/Max
__device__ __forceinline__ unsigned fenc(float x) {
    unsigned u = __float_as_uint(x);
    return (u & 0x80000000u) ? ~u : (u | 0x80000000u);
}
__device__ __forceinline__ float fdec(unsigned e) {
    return (e & 0x80000000u) ? __uint_as_float(e ^ 0x80000000u)
                             : __uint_as_float(~e);
}

// K0: zero accumulators / counters (must run every replay)
__global__ void k_zero() {
    int i = blockIdx.x * blockDim.x + threadIdx.x;
    float4 z = make_float4(0.f, 0.f, 0.f, 0.f);
    if (i < NN * HD / 4) ((float4*)g_agg1)[i] = z;
    if (i < NN)          g_deg[i] = 0;
    if (i < MM * 2 / 4)  ((float4*)g_agg2)[i] = z;
    if (i == 0) { g_fcnt = 0; g_mn = 0xFFFFFFFFu; g_mx = 0u; }
}

// K1: in-degree histogram over dst
__global__ void k_deg(const int* __restrict__ dst) {
    int e = blockIdx.x * blockDim.x + threadIdx.x;
    if (e < NE) atomicAdd(&g_deg[dst[e]], 1);
}

// K2: dinv = rsqrt(deg + 1)   (+1 = self loop; always > 0)
__global__ void k_dinv() {
    int i = blockIdx.x * blockDim.x + threadIdx.x;
    if (i < NN) g_dinv[i] = rsqrtf((float)(g_deg[i] + 1));
}

// K3: h = x @ W1   ([NN,100] @ [100,16]); 16 nodes per 256-thread block
__global__ void k_gemm1(const float* __restrict__ x, const float* __restrict__ W1) {
    __shared__ float sW[FIN * HD];     // 6.4 KB
    __shared__ float sx[16 * FIN];     // 6.4 KB
    int t = threadIdx.x;
    for (int i = t; i < FIN * HD; i += 256) sW[i] = W1[i];
    int node0 = blockIdx.x * 16;
    for (int i = t; i < 16 * FIN; i += 256) sx[i] = x[(size_t)node0 * FIN + i];
    __syncthreads();
    int node = t >> 4, col = t & 15;
    float acc = 0.f;
#pragma unroll 4
    for (int k = 0; k < FIN; k++)
        acc = fmaf(sx[node * FIN + k], sW[k * HD + col], acc);
    g_h[(size_t)node0 * HD + t] = acc;   // coalesced: (node0+node)*16+col
}

// K4: the heavy pass. Per edge: agg1[d] += dinv[s]*dinv[d]*h[s] via red.v4.f32,
//     and compact edges with d%20==0 for layer 2.
__global__ void k_edge(const int* __restrict__ src, const int* __restrict__ dst) {
    int e = blockIdx.x * blockDim.x + threadIdx.x;
    if (e >= NE) return;
    int s = src[e], d = dst[e];
    float norm = g_dinv[s] * g_dinv[d];
    const float4* hs = (const float4*)(g_h + (size_t)s * HD);
    float4* ad = (float4*)(g_agg1 + (size_t)d * HD);
#pragma unroll
    for (int j = 0; j < 4; j++) {
        float4 v = hs[j];
        v.x *= norm; v.y *= norm; v.z *= norm; v.w *= norm;
        asm volatile("red.global.add.v4.f32 [%0], {%1,%2,%3,%4};"
                     :: "l"(ad + j), "f"(v.x), "f"(v.y), "f"(v.z), "f"(v.w)
                     : "memory");
    }
    if (d % 20 == 0) {
        int p = atomicAdd(&g_fcnt, 1);
        if (p < FCAP) { g_fsrc[p] = s; g_fidx[p] = d / 20; g_fnorm[p] = norm; }
    }
}

// K5: h1 = relu(agg1 + dinv^2*h + b1); h2lin = h1 @ W2   ([16]->[2])
__global__ void k_l1fin(const float* __restrict__ b1, const float* __restrict__ W2) {
    int i = blockIdx.x * blockDim.x + threadIdx.x;
    if (i >= NN) return;
    float di2 = g_dinv[i]; di2 *= di2;
    const float4* a4 = (const float4*)(g_agg1 + (size_t)i * HD);
    const float4* h4 = (const float4*)(g_h + (size_t)i * HD);
    float o0 = 0.f, o1 = 0.f;
#pragma unroll
    for (int j = 0; j < 4; j++) {
        float4 a = a4[j], h = h4[j];
        float v;
        v = fmaxf(fmaf(di2, h.x, a.x) + __ldg(b1 + 4 * j + 0), 0.f);
        o0 = fmaf(v, __ldg(W2 + 8 * j + 0), o0); o1 = fmaf(v, __ldg(W2 + 8 * j + 1), o1);
        v = fmaxf(fmaf(di2, h.y, a.y) + __ldg(b1 + 4 * j + 1), 0.f);
        o0 = fmaf(v, __ldg(W2 + 8 * j + 2), o0); o1 = fmaf(v, __ldg(W2 + 8 * j + 3), o1);
        v = fmaxf(fmaf(di2, h.z, a.z) + __ldg(b1 + 4 * j + 2), 0.f);
        o0 = fmaf(v, __ldg(W2 + 8 * j + 4), o0); o1 = fmaf(v, __ldg(W2 + 8 * j + 5), o1);
        v = fmaxf(fmaf(di2, h.w, a.w) + __ldg(b1 + 4 * j + 3), 0.f);
        o0 = fmaf(v, __ldg(W2 + 8 * j + 6), o0); o1 = fmaf(v, __ldg(W2 + 8 * j + 7), o1);
    }
    g_h2[2 * i] = o0; g_h2[2 * i + 1] = o1;
}

// K6: layer-2 aggregation over the compacted edge subset
__global__ void k_edge2() {
    int e = blockIdx.x * blockDim.x + threadIdx.x;
    int cnt = g_fcnt; if (cnt > FCAP) cnt = FCAP;
    if (e >= cnt) return;
    int s = g_fsrc[e], r = g_fidx[e];
    float nm = g_fnorm[e];
    atomicAdd(&g_agg2[2 * r + 0], nm * g_h2[2 * s + 0]);
    atomicAdd(&g_agg2[2 * r + 1], nm * g_h2[2 * s + 1]);
}

// K7: finalize sampled nodes -> log_softmax -> BP rows + global min/max
__global__ void k_samp(const float* __restrict__ b2, const float* __restrict__ tE,
                       const float* __restrict__ cE, const float* __restrict__ pI) {
    int r = blockIdx.x * blockDim.x + threadIdx.x;
    float lmin = 3.4e38f, lmax = -3.4e38f;
    if (r < MM) {
        int i = r * 20;
        float di2 = g_dinv[i]; di2 *= di2;
        float l0 = g_agg2[2 * r + 0] + di2 * g_h2[2 * i + 0] + __ldg(b2 + 0);
        float l1 = g_agg2[2 * r + 1] + di2 * g_h2[2 * i + 1] + __ldg(b2 + 1);
        float m = fmaxf(l0, l1);
        float lse = m + logf(expf(l0 - m) + expf(l1 - m));
        float a = tE[r], b = cE[r], c = pI[r], d0 = l0 - lse, d1 = l1 - lse;
        g_bp[5 * r + 0] = a; g_bp[5 * r + 1] = b; g_bp[5 * r + 2] = c;
        g_bp[5 * r + 3] = d0; g_bp[5 * r + 4] = d1;
        lmin = fminf(fminf(a, b), fminf(c, fminf(d0, d1)));
        lmax = fmaxf(fmaxf(a, b), fmaxf(c, fmaxf(d0, d1)));
    }
#pragma unroll
    for (int o = 16; o; o >>= 1) {
        lmin = fminf(lmin, __shfl_xor_sync(0xffffffffu, lmin, o));
        lmax = fmaxf(lmax, __shfl_xor_sync(0xffffffffu, lmax, o));
    }
    if ((threadIdx.x & 31) == 0) {
        atomicMin(&g_mn, fenc(lmin));
        atomicMax(&g_mx, fenc(lmax));
    }
}

// K8: min-max normalize + 3-layer MLP + sigmoid
__global__ void k_mlp(const float* __restrict__ W1, const float* __restrict__ b1,
                      const float* __restrict__ W2, const float* __restrict__ b2,
                      const float* __restrict__ W3, const float* __restrict__ b3,
                      float* __restrict__ out) {
    __shared__ float sW1[5 * 80], sb1[80], sW2[80 * 10], sb2[10], sW3[10];
    __shared__ float sB3, sMn, sInv;
    int t = threadIdx.x;
    for (int i = t; i < 400; i += 256) sW1[i] = W1[i];
    for (int i = t; i < 800; i += 256) sW2[i] = W2[i];
    if (t < 80) sb1[t] = b1[t];
    if (t < 10) { sb2[t] = b2[t]; sW3[t] = W3[t]; }
    if (t == 0) {
        sB3 = b3[0];
        float mn = fdec(g_mn), mx = fdec(g_mx);
        sMn = mn; sInv = 1.f / (mx - mn);
    }
    __syncthreads();
    int r = blockIdx.x * blockDim.x + t;
    if (r >= MM) return;
    float bp[5];
#pragma unroll
    for (int k = 0; k < 5; k++) bp[k] = (g_bp[5 * r + k] - sMn) * sInv;
    float acc[10];
#pragma unroll
    for (int q = 0; q < 10; q++) acc[q] = sb2[q];
    for (int j = 0; j < 80; j++) {
        float s = sb1[j];
#pragma unroll
        for (int k = 0; k < 5; k++) s = fmaf(bp[k], sW1[k * 80 + j], s);
        s = fmaxf(s, 0.f);
#pragma unroll
        for (int q = 0; q < 10; q++) acc[q] = fmaf(s, sW2[j * 10 + q], acc[q]);
    }
    float o = sB3;
#pragma unroll
    for (int q = 0; q < 10; q++) o = fmaf(fmaxf(acc[q], 0.f), sW3[q], o);
    out[r] = 1.f / (1.f + expf(-o));
}

extern "C" void kernel_launch(void* const* d_in, const int* in_sizes, int n_in,
                              void* d_out, int out_size) {
    const int*   ei     = (const int*)d_in[0];     // batch1_edge_index [2,E]
    const float* x      = (const float*)d_in[1];   // batch1_x [N,100]
    // d_in[2], d_in[3]: batch2 (gcnt_out unused)  -- skipped
    const float* transE = (const float*)d_in[4];
    const float* complE = (const float*)d_in[5];
    const float* path   = (const float*)d_in[6];
    // d_in[7]: edit_input unused -- skipped
    const float* ghW1 = (const float*)d_in[8];
    const float* ghb1 = (const float*)d_in[9];
    const float* ghW2 = (const float*)d_in[10];
    const float* ghb2 = (const float*)d_in[11];
    // d_in[12..15]: gt weights unused -- skipped
    const float* mW1 = (const float*)d_in[16];
    const float* mb1 = (const float*)d_in[17];
    const float* mW2 = (const float*)d_in[18];
    const float* mb2 = (const float*)d_in[19];
    const float* mW3 = (const float*)d_in[20];
    const float* mb3 = (const float*)d_in[21];

    const int* src = ei;
    const int* dst = ei + NE;
    float* out = (float*)d_out;

    k_zero <<<3125, 256>>>();
    k_deg  <<<NE / 256, 256>>>(dst);
    k_dinv <<<(NN + 255) / 256, 256>>>();
    k_gemm1<<<NN / 16, 256>>>(x, ghW1);
    k_edge <<<NE / 256, 256>>>(src, dst);
    k_l1fin<<<(NN + 255) / 256, 256>>>(ghb1, ghW2);
    k_edge2<<<FCAP / 256, 256>>>();
    k_samp <<<(MM + 255) / 256, 256>>>(ghb2, transE, complE, path);
    k_mlp  <<<(MM + 255) / 256, 256>>>(mW1, mb1, mW2, mb2, mW3, mb3, out);
}

// round 2
// speedup vs baseline: 1.8579x; 1.8579x over previous
#include <cuda_runtime.h>

// Problem constants (fixed by the dataset)
#define NN   200000      // nodes
#define NE   6400000     // edges
#define MM   10000       // NN/20 sampled rows
#define FIN  100
#define HD   16
#define FCAP 1048576     // capacity for filtered (dst%20==0) edges; expected ~320k

// ---------------- scratch (device globals; no allocation allowed) ----------
__device__ int      g_deg[NN];
__device__ float    g_dinv[NN];
__device__ float    g_hs[NN * HD];      // dinv * (x @ W1)   (pre-scaled)
__device__ float    g_agg1[NN * HD];    // sum of hs over in-edges
__device__ float    g_h2s[NN * 2];      // dinv * (relu(h1) @ W2)
__device__ float    g_agg2[MM * 2];     // layer-2 aggregation (sampled dst only)
__device__ float    g_bp[MM * 5];       // BP_input rows
__device__ int      g_fs[FCAP];         // compacted src
__device__ int      g_fr[FCAP];         // compacted dst/20
__device__ int      g_fcnt;
__device__ unsigned g_mn, g_mx;         // encoded float min/max

// monotonic float<->uint encoding for atomicMin/Max
__device__ __forceinline__ unsigned fenc(float x) {
    unsigned u = __float_as_uint(x);
    return (u & 0x80000000u) ? ~u : (u | 0x80000000u);
}
__device__ __forceinline__ float fdec(unsigned e) {
    return (e & 0x80000000u) ? __uint_as_float(e ^ 0x80000000u)
                             : __uint_as_float(~e);
}

// K0: zero accumulators / counters (must run every replay)
__global__ void k_zero() {
    int i = blockIdx.x * blockDim.x + threadIdx.x;
    float4 z = make_float4(0.f, 0.f, 0.f, 0.f);
    if (i < NN * HD / 4) ((float4*)g_agg1)[i] = z;
    if (i < NN)          g_deg[i] = 0;
    if (i < MM * 2 / 4)  ((float4*)g_agg2)[i] = z;
    if (i == 0) { g_fcnt = 0; g_mn = 0xFFFFFFFFu; g_mx = 0u; }
}

// K1: in-degree histogram over dst (4 edges/thread, int4 loads)
__global__ void k_deg(const int* __restrict__ dst) {
    int t = blockIdx.x * blockDim.x + threadIdx.x;
    int4 d = ((const int4*)dst)[t];
    atomicAdd(&g_deg[d.x], 1);
    atomicAdd(&g_deg[d.y], 1);
    atomicAdd(&g_deg[d.z], 1);
    atomicAdd(&g_deg[d.w], 1);
}

// K2: dinv = rsqrt(deg + 1)   (+1 = self loop; always > 0)
__global__ void k_dinv() {
    int i = blockIdx.x * blockDim.x + threadIdx.x;
    if (i < NN) g_dinv[i] = rsqrtf((float)(g_deg[i] + 1));
}

// K3: hs = dinv * (x @ W1). 64 nodes/block, each thread: 1 node x 4 cols.
//     Per k-step: 1 LDS.32 (x, broadcast) + 1 LDS.128 (W row chunk) -> 4 FMA.
__global__ void k_gemm1(const float* __restrict__ x, const float* __restrict__ W1) {
    __shared__ float4 sW[FIN * 4];     // [k][cg] -> cols 4cg..4cg+3   (6.4 KB)
    __shared__ float  sx[64 * FIN];    // 25.6 KB
    int t = threadIdx.x;
    const float4* W4 = (const float4*)W1;
    for (int i = t; i < FIN * 4; i += 256) sW[i] = W4[i];
    const float4* x4 = (const float4*)(x + (size_t)blockIdx.x * 64 * FIN);
    float4* sx4 = (float4*)sx;
    for (int i = t; i < 64 * FIN / 4; i += 256) sx4[i] = x4[i];
    __syncthreads();
    int node = t >> 2, cg = t & 3;
    const float* xr = sx + node * FIN;
    float4 acc = make_float4(0.f, 0.f, 0.f, 0.f);
#pragma unroll 5
    for (int k = 0; k < FIN; k++) {
        float xv = xr[k];
        float4 w = sW[k * 4 + cg];
        acc.x = fmaf(xv, w.x, acc.x);
        acc.y = fmaf(xv, w.y, acc.y);
        acc.z = fmaf(xv, w.z, acc.z);
        acc.w = fmaf(xv, w.w, acc.w);
    }
    int gn = blockIdx.x * 64 + node;
    float di = g_dinv[gn];
    acc.x *= di; acc.y *= di; acc.z *= di; acc.w *= di;
    ((float4*)g_hs)[gn * 4 + cg] = acc;
}

// per-edge: agg1[d] += hs[s]  (norm folded into hs and the finalize)
__device__ __forceinline__ void edge_red(int s, int d) {
    const float4* hs = (const float4*)(g_hs + (size_t)s * HD);
    float4* ad = (float4*)(g_agg1 + (size_t)d * HD);
#pragma unroll
    for (int j = 0; j < 4; j++) {
        float4 v = hs[j];
        asm volatile("red.global.add.v4.f32 [%0], {%1,%2,%3,%4};"
                     :: "l"(ad + j), "f"(v.x), "f"(v.y), "f"(v.z), "f"(v.w)
                     : "memory");
    }
}

// K4: heavy pass. 4 edges/thread via int4. Compaction of d%20==0 edges uses
//     warp scan + ONE atomicAdd per block (kills single-address contention).
__global__ void k_edge(const int* __restrict__ src, const int* __restrict__ dst) {
    int t = blockIdx.x * blockDim.x + threadIdx.x;
    int4 s = ((const int4*)src)[t];
    int4 d = ((const int4*)dst)[t];

    edge_red(s.x, d.x);
    edge_red(s.y, d.y);
    edge_red(s.z, d.z);
    edge_red(s.w, d.w);

    int m0 = (d.x % 20 == 0), m1 = (d.y % 20 == 0);
    int m2 = (d.z % 20 == 0), m3 = (d.w % 20 == 0);
    int cnt = m0 + m1 + m2 + m3;

    int lane = threadIdx.x & 31, wid = threadIdx.x >> 5;
    int sc = cnt;
#pragma unroll
    for (int o = 1; o < 32; o <<= 1) {
        int n = __shfl_up_sync(0xffffffffu, sc, o);
        if (lane >= o) sc += n;
    }
    int myOff = sc - cnt;

    __shared__ int wTot[8], wBase[8], blkBase;
    if (lane == 31) wTot[wid] = sc;
    __syncthreads();
    if (threadIdx.x == 0) {
        int tot = 0;
#pragma unroll
        for (int w = 0; w < 8; w++) { wBase[w] = tot; tot += wTot[w]; }
        blkBase = atomicAdd(&g_fcnt, tot);
    }
    __syncthreads();
    int pos = blkBase + wBase[wid] + myOff;
    if (m0 && pos < FCAP) { g_fs[pos] = s.x; g_fr[pos] = d.x / 20; pos++; }
    if (m1 && pos < FCAP) { g_fs[pos] = s.y; g_fr[pos] = d.y / 20; pos++; }
    if (m2 && pos < FCAP) { g_fs[pos] = s.z; g_fr[pos] = d.z / 20; pos++; }
    if (m3 && pos < FCAP) { g_fs[pos] = s.w; g_fr[pos] = d.w / 20; pos++; }
}

// K5: h1 = relu(dinv*(agg1 + hs) + b1); h2s = dinv*(h1 @ W2)
__global__ void k_l1fin(const float* __restrict__ b1, const float* __restrict__ W2) {
    int i = blockIdx.x * blockDim.x + threadIdx.x;
    if (i >= NN) return;
    float di = g_dinv[i];
    const float4* a4 = (const float4*)(g_agg1 + (size_t)i * HD);
    const float4* h4 = (const float4*)(g_hs + (size_t)i * HD);
    float o0 = 0.f, o1 = 0.f;
#pragma unroll
    for (int j = 0; j < 4; j++) {
        float4 a = a4[j], h = h4[j];
        float v;
        v = fmaxf(fmaf(di, a.x + h.x, __ldg(b1 + 4 * j + 0)), 0.f);
        o0 = fmaf(v, __ldg(W2 + 8 * j + 0), o0); o1 = fmaf(v, __ldg(W2 + 8 * j + 1), o1);
        v = fmaxf(fmaf(di, a.y + h.y, __ldg(b1 + 4 * j + 1)), 0.f);
        o0 = fmaf(v, __ldg(W2 + 8 * j + 2), o0); o1 = fmaf(v, __ldg(W2 + 8 * j + 3), o1);
        v = fmaxf(fmaf(di, a.z + h.z, __ldg(b1 + 4 * j + 2)), 0.f);
        o0 = fmaf(v, __ldg(W2 + 8 * j + 4), o0); o1 = fmaf(v, __ldg(W2 + 8 * j + 5), o1);
        v = fmaxf(fmaf(di, a.w + h.w, __ldg(b1 + 4 * j + 3)), 0.f);
        o0 = fmaf(v, __ldg(W2 + 8 * j + 6), o0); o1 = fmaf(v, __ldg(W2 + 8 * j + 7), o1);
    }
    float2* out = (float2*)(g_h2s + 2 * i);
    *out = make_float2(di * o0, di * o1);
}

// K6: layer-2 aggregation over the compacted edge subset
__global__ void k_edge2() {
    int e = blockIdx.x * blockDim.x + threadIdx.x;
    int cnt = g_fcnt; if (cnt > FCAP) cnt = FCAP;
    if (e >= cnt) return;
    int s = g_fs[e], r = g_fr[e];
    float2 h2 = ((const float2*)g_h2s)[s];
    float2* ad = ((float2*)g_agg2) + r;
    asm volatile("red.global.add.v2.f32 [%0], {%1,%2};"
                 :: "l"(ad), "f"(h2.x), "f"(h2.y) : "memory");
}

// K7: finalize sampled nodes -> log_softmax -> BP rows + global min/max
__global__ void k_samp(const float* __restrict__ b2, const float* __restrict__ tE,
                       const float* __restrict__ cE, const float* __restrict__ pI) {
    int r = blockIdx.x * blockDim.x + threadIdx.x;
    float lmin = 3.4e38f, lmax = -3.4e38f;
    if (r < MM) {
        int i = r * 20;
        float di = g_dinv[i];
        float2 h2 = ((const float2*)g_h2s)[i];
        float l0 = di * (g_agg2[2 * r + 0] + h2.x) + __ldg(b2 + 0);
        float l1 = di * (g_agg2[2 * r + 1] + h2.y) + __ldg(b2 + 1);
        float m = fmaxf(l0, l1);
        float lse = m + logf(expf(l0 - m) + expf(l1 - m));
        float a = tE[r], b = cE[r], c = pI[r], d0 = l0 - lse, d1 = l1 - lse;
        g_bp[5 * r + 0] = a; g_bp[5 * r + 1] = b; g_bp[5 * r + 2] = c;
        g_bp[5 * r + 3] = d0; g_bp[5 * r + 4] = d1;
        lmin = fminf(fminf(a, b), fminf(c, fminf(d0, d1)));
        lmax = fmaxf(fmaxf(a, b), fmaxf(c, fmaxf(d0, d1)));
    }
#pragma unroll
    for (int o = 16; o; o >>= 1) {
        lmin = fminf(lmin, __shfl_xor_sync(0xffffffffu, lmin, o));
        lmax = fmaxf(lmax, __shfl_xor_sync(0xffffffffu, lmax, o));
    }
    if ((threadIdx.x & 31) == 0) {
        atomicMin(&g_mn, fenc(lmin));
        atomicMax(&g_mx, fenc(lmax));
    }
}

// K8: min-max normalize + 3-layer MLP + sigmoid
__global__ void k_mlp(const float* __restrict__ W1, const float* __restrict__ b1,
                      const float* __restrict__ W2, const float* __restrict__ b2,
                      const float* __restrict__ W3, const float* __restrict__ b3,
                      float* __restrict__ out) {
    __shared__ float sW1[5 * 80], sb1[80], sW2[80 * 10], sb2[10], sW3[10];
    __shared__ float sB3, sMn, sInv;
    int t = threadIdx.x;
    for (int i = t; i < 400; i += 256) sW1[i] = W1[i];
    for (int i = t; i < 800; i += 256) sW2[i] = W2[i];
    if (t < 80) sb1[t] = b1[t];
    if (t < 10) { sb2[t] = b2[t]; sW3[t] = W3[t]; }
    if (t == 0) {
        sB3 = b3[0];
        float mn = fdec(g_mn), mx = fdec(g_mx);
        sMn = mn; sInv = 1.f / (mx - mn);
    }
    __syncthreads();
    int r = blockIdx.x * blockDim.x + t;
    if (r >= MM) return;
    float bp[5];
#pragma unroll
    for (int k = 0; k < 5; k++) bp[k] = (g_bp[5 * r + k] - sMn) * sInv;
    float acc[10];
#pragma unroll
    for (int q = 0; q < 10; q++) acc[q] = sb2[q];
    for (int j = 0; j < 80; j++) {
        float s = sb1[j];
#pragma unroll
        for (int k = 0; k < 5; k++) s = fmaf(bp[k], sW1[k * 80 + j], s);
        s = fmaxf(s, 0.f);
#pragma unroll
        for (int q = 0; q < 10; q++) acc[q] = fmaf(s, sW2[j * 10 + q], acc[q]);
    }
    float o = sB3;
#pragma unroll
    for (int q = 0; q < 10; q++) o = fmaf(fmaxf(acc[q], 0.f), sW3[q], o);
    out[r] = 1.f / (1.f + expf(-o));
}

extern "C" void kernel_launch(void* const* d_in, const int* in_sizes, int n_in,
                              void* d_out, int out_size) {
    const int*   ei     = (const int*)d_in[0];     // batch1_edge_index [2,E]
    const float* x      = (const float*)d_in[1];   // batch1_x [N,100]
    const float* transE = (const float*)d_in[4];
    const float* complE = (const float*)d_in[5];
    const float* path   = (const float*)d_in[6];
    const float* ghW1 = (const float*)d_in[8];
    const float* ghb1 = (const float*)d_in[9];
    const float* ghW2 = (const float*)d_in[10];
    const float* ghb2 = (const float*)d_in[11];
    const float* mW1 = (const float*)d_in[16];
    const float* mb1 = (const float*)d_in[17];
    const float* mW2 = (const float*)d_in[18];
    const float* mb2 = (const float*)d_in[19];
    const float* mW3 = (const float*)d_in[20];
    const float* mb3 = (const float*)d_in[21];

    const int* src = ei;
    const int* dst = ei + NE;
    float* out = (float*)d_out;

    k_zero <<<3125, 256>>>();
    k_deg  <<<NE / 1024, 256>>>(dst);               // 4 edges/thread
    k_dinv <<<(NN + 255) / 256, 256>>>();
    k_gemm1<<<NN / 64, 256>>>(x, ghW1);
    k_edge <<<NE / 1024, 256>>>(src, dst);          // 4 edges/thread
    k_l1fin<<<(NN + 255) / 256, 256>>>(ghb1, ghW2);
    k_edge2<<<FCAP / 256, 256>>>();
    k_samp <<<(MM + 255) / 256, 256>>>(ghb2, transE, complE, path);
    k_mlp  <<<(MM + 255) / 256, 256>>>(mW1, mb1, mW2, mb2, mW3, mb3, out);
}

// round 3
// speedup vs baseline: 3.0154x; 1.6230x over previous
#include <cuda_runtime.h>

// Problem constants (fixed by the dataset)
#define NN   200000      // nodes
#define NE   6400000     // edges
#define MM   10000       // NN/20 sampled rows
#define FIN  100
#define HD   16
#define FCAP 1048576     // capacity for filtered (dst%20==0) edges; expected ~320k

// ---------------- scratch (device globals; no allocation allowed) ----------
__device__ int      g_deg[NN];
__device__ float    g_dinv[NN];
__device__ float    g_hs[NN * HD];      // dinv * (x @ W1)   (pre-scaled)
__device__ float    g_agg1[NN * HD];    // sum of hs over in-edges
__device__ float    g_h2s[NN * 2];      // dinv * (relu(h1) @ W2)
__device__ float    g_agg2[MM * 2];     // layer-2 aggregation (sampled dst only)
__device__ float    g_bp[MM * 5];       // BP_input rows
__device__ int      g_fs[FCAP];         // compacted src
__device__ int      g_fr[FCAP];         // compacted dst/20
__device__ int      g_fcnt;
__device__ unsigned g_mn, g_mx;         // encoded float min/max

// monotonic float<->uint encoding for atomicMin/Max
__device__ __forceinline__ unsigned fenc(float x) {
    unsigned u = __float_as_uint(x);
    return (u & 0x80000000u) ? ~u : (u | 0x80000000u);
}
__device__ __forceinline__ float fdec(unsigned e) {
    return (e & 0x80000000u) ? __uint_as_float(e ^ 0x80000000u)
                             : __uint_as_float(~e);
}

// K0: zero accumulators / counters (must run every replay)
__global__ void k_zero() {
    int i = blockIdx.x * blockDim.x + threadIdx.x;
    float4 z = make_float4(0.f, 0.f, 0.f, 0.f);
    if (i < NN * HD / 4) ((float4*)g_agg1)[i] = z;
    if (i < NN)          g_deg[i] = 0;
    if (i < MM * 2 / 4)  ((float4*)g_agg2)[i] = z;
    if (i == 0) { g_fcnt = 0; g_mn = 0xFFFFFFFFu; g_mx = 0u; }
}

// K1: in-degree histogram over dst (4 edges/thread, int4 loads)
__global__ void k_deg(const int* __restrict__ dst) {
    int t = blockIdx.x * blockDim.x + threadIdx.x;
    int4 d = ((const int4*)dst)[t];
    atomicAdd(&g_deg[d.x], 1);
    atomicAdd(&g_deg[d.y], 1);
    atomicAdd(&g_deg[d.z], 1);
    atomicAdd(&g_deg[d.w], 1);
}

// K2: dinv = rsqrt(deg + 1)   (+1 = self loop; always > 0)
__global__ void k_dinv() {
    int i = blockIdx.x * blockDim.x + threadIdx.x;
    if (i < NN) g_dinv[i] = rsqrtf((float)(g_deg[i] + 1));
}

// K3: hs = dinv * (x @ W1). 64 threads/block, 1 node per lane, 16 cols in regs.
//     Per k: 1 LDS.32 (x, 4-way conflict) + 4 broadcast LDS.128 (W) -> 16 FMA.
__global__ void __launch_bounds__(64) k_gemm1(const float* __restrict__ x,
                                              const float* __restrict__ W1) {
    __shared__ float  sx[64 * FIN];    // 25.6 KB
    __shared__ float4 sW[FIN * 4];     // 6.4 KB: sW[k*4+g] = cols 4g..4g+3 of row k
    int t = threadIdx.x;
    const float4* W4 = (const float4*)W1;
    for (int i = t; i < FIN * 4; i += 64) sW[i] = W4[i];
    const float4* x4 = (const float4*)(x + (size_t)blockIdx.x * 64 * FIN);
    float4* sx4 = (float4*)sx;
#pragma unroll
    for (int i = 0; i < 25; i++) sx4[i * 64 + t] = x4[i * 64 + t];
    __syncthreads();

    float acc[16];
#pragma unroll
    for (int c = 0; c < 16; c++) acc[c] = 0.f;
    const float* xr = sx + t * FIN;
#pragma unroll 4
    for (int k = 0; k < FIN; k++) {
        float xv = xr[k];
        float4 w0 = sW[k * 4 + 0], w1 = sW[k * 4 + 1];
        float4 w2 = sW[k * 4 + 2], w3 = sW[k * 4 + 3];
        acc[0]  = fmaf(xv, w0.x, acc[0]);  acc[1]  = fmaf(xv, w0.y, acc[1]);
        acc[2]  = fmaf(xv, w0.z, acc[2]);  acc[3]  = fmaf(xv, w0.w, acc[3]);
        acc[4]  = fmaf(xv, w1.x, acc[4]);  acc[5]  = fmaf(xv, w1.y, acc[5]);
        acc[6]  = fmaf(xv, w1.z, acc[6]);  acc[7]  = fmaf(xv, w1.w, acc[7]);
        acc[8]  = fmaf(xv, w2.x, acc[8]);  acc[9]  = fmaf(xv, w2.y, acc[9]);
        acc[10] = fmaf(xv, w2.z, acc[10]); acc[11] = fmaf(xv, w2.w, acc[11]);
        acc[12] = fmaf(xv, w3.x, acc[12]); acc[13] = fmaf(xv, w3.y, acc[13]);
        acc[14] = fmaf(xv, w3.z, acc[14]); acc[15] = fmaf(xv, w3.w, acc[15]);
    }
    int gn = blockIdx.x * 64 + t;
    float di = g_dinv[gn];
    float4* o = (float4*)(g_hs + (size_t)gn * HD);
#pragma unroll
    for (int g = 0; g < 4; g++)
        o[g] = make_float4(di * acc[4 * g + 0], di * acc[4 * g + 1],
                           di * acc[4 * g + 2], di * acc[4 * g + 3]);
}

// K4: heavy pass, warp-cooperative. Each thread owns 1 edge; gather + red are
//     done by 4 adjacent lanes per edge (8 edges per sub-iteration) so each
//     warp LDG/red instruction touches 8 cache lines instead of 32.
__global__ void __launch_bounds__(512) k_edge(const int* __restrict__ src,
                                              const int* __restrict__ dst) {
    int t = blockIdx.x * blockDim.x + threadIdx.x;   // one edge per thread
    int lane = threadIdx.x & 31, wid = threadIdx.x >> 5;
    int s = src[t], d = dst[t];
    int chunk = lane & 3;

#pragma unroll
    for (int sub = 0; sub < 4; sub++) {
        int eLane = sub * 8 + (lane >> 2);
        int ss = __shfl_sync(0xffffffffu, s, eLane);
        int dd = __shfl_sync(0xffffffffu, d, eLane);
        float4 v = ((const float4*)g_hs)[ss * 4 + chunk];
        float4* ad = ((float4*)g_agg1) + dd * 4 + chunk;
        asm volatile("red.global.add.v4.f32 [%0], {%1,%2,%3,%4};"
                     :: "l"(ad), "f"(v.x), "f"(v.y), "f"(v.z), "f"(v.w)
                     : "memory");
    }

    // compaction of d%20==0 edges: ballot per warp, one atomic per block
    int m = (d % 20 == 0);
    unsigned bal = __ballot_sync(0xffffffffu, m);
    int wcnt = __popc(bal);
    int myOff = __popc(bal & ((1u << lane) - 1));

    __shared__ int wTot[16], wBase[16], blkBase;
    if (lane == 0) wTot[wid] = wcnt;
    __syncthreads();
    if (threadIdx.x == 0) {
        int tot = 0;
#pragma unroll
        for (int w = 0; w < 16; w++) { wBase[w] = tot; tot += wTot[w]; }
        blkBase = atomicAdd(&g_fcnt, tot);
    }
    __syncthreads();
    if (m) {
        int pos = blkBase + wBase[wid] + myOff;
        if (pos < FCAP) { g_fs[pos] = s; g_fr[pos] = d / 20; }
    }
}

// K5: h1 = relu(dinv*(agg1 + hs) + b1); h2s = dinv*(h1 @ W2)
__global__ void k_l1fin(const float* __restrict__ b1, const float* __restrict__ W2) {
    int i = blockIdx.x * blockDim.x + threadIdx.x;
    if (i >= NN) return;
    float di = g_dinv[i];
    const float4* a4 = (const float4*)(g_agg1 + (size_t)i * HD);
    const float4* h4 = (const float4*)(g_hs + (size_t)i * HD);
    float o0 = 0.f, o1 = 0.f;
#pragma unroll
    for (int j = 0; j < 4; j++) {
        float4 a = a4[j], h = h4[j];
        float v;
        v = fmaxf(fmaf(di, a.x + h.x, __ldg(b1 + 4 * j + 0)), 0.f);
        o0 = fmaf(v, __ldg(W2 + 8 * j + 0), o0); o1 = fmaf(v, __ldg(W2 + 8 * j + 1), o1);
        v = fmaxf(fmaf(di, a.y + h.y, __ldg(b1 + 4 * j + 1)), 0.f);
        o0 = fmaf(v, __ldg(W2 + 8 * j + 2), o0); o1 = fmaf(v, __ldg(W2 + 8 * j + 3), o1);
        v = fmaxf(fmaf(di, a.z + h.z, __ldg(b1 + 4 * j + 2)), 0.f);
        o0 = fmaf(v, __ldg(W2 + 8 * j + 4), o0); o1 = fmaf(v, __ldg(W2 + 8 * j + 5), o1);
        v = fmaxf(fmaf(di, a.w + h.w, __ldg(b1 + 4 * j + 3)), 0.f);
        o0 = fmaf(v, __ldg(W2 + 8 * j + 6), o0); o1 = fmaf(v, __ldg(W2 + 8 * j + 7), o1);
    }
    float2* out = (float2*)(g_h2s + 2 * i);
    *out = make_float2(di * o0, di * o1);
}

// K6: layer-2 aggregation over the compacted edge subset
__global__ void k_edge2() {
    int e = blockIdx.x * blockDim.x + threadIdx.x;
    int cnt = g_fcnt; if (cnt > FCAP) cnt = FCAP;
    if (e >= cnt) return;
    int s = g_fs[e], r = g_fr[e];
    float2 h2 = ((const float2*)g_h2s)[s];
    float2* ad = ((float2*)g_agg2) + r;
    asm volatile("red.global.add.v2.f32 [%0], {%1,%2};"
                 :: "l"(ad), "f"(h2.x), "f"(h2.y) : "memory");
}

// K7: finalize sampled nodes -> log_softmax -> BP rows + global min/max
__global__ void k_samp(const float* __restrict__ b2, const float* __restrict__ tE,
                       const float* __restrict__ cE, const float* __restrict__ pI) {
    int r = blockIdx.x * blockDim.x + threadIdx.x;
    float lmin = 3.4e38f, lmax = -3.4e38f;
    if (r < MM) {
        int i = r * 20;
        float di = g_dinv[i];
        float2 h2 = ((const float2*)g_h2s)[i];
        float l0 = di * (g_agg2[2 * r + 0] + h2.x) + __ldg(b2 + 0);
        float l1 = di * (g_agg2[2 * r + 1] + h2.y) + __ldg(b2 + 1);
        float m = fmaxf(l0, l1);
        float lse = m + logf(expf(l0 - m) + expf(l1 - m));
        float a = tE[r], b = cE[r], c = pI[r], d0 = l0 - lse, d1 = l1 - lse;
        g_bp[5 * r + 0] = a; g_bp[5 * r + 1] = b; g_bp[5 * r + 2] = c;
        g_bp[5 * r + 3] = d0; g_bp[5 * r + 4] = d1;
        lmin = fminf(fminf(a, b), fminf(c, fminf(d0, d1)));
        lmax = fmaxf(fmaxf(a, b), fmaxf(c, fmaxf(d0, d1)));
    }
#pragma unroll
    for (int o = 16; o; o >>= 1) {
        lmin = fminf(lmin, __shfl_xor_sync(0xffffffffu, lmin, o));
        lmax = fmaxf(lmax, __shfl_xor_sync(0xffffffffu, lmax, o));
    }
    if ((threadIdx.x & 31) == 0) {
        atomicMin(&g_mn, fenc(lmin));
        atomicMax(&g_mx, fenc(lmax));
    }
}

// K8: min-max normalize + 3-layer MLP + sigmoid
__global__ void k_mlp(const float* __restrict__ W1, const float* __restrict__ b1,
                      const float* __restrict__ W2, const float* __restrict__ b2,
                      const float* __restrict__ W3, const float* __restrict__ b3,
                      float* __restrict__ out) {
    __shared__ float sW1[5 * 80], sb1[80], sW2[80 * 10], sb2[10], sW3[10];
    __shared__ float sB3, sMn, sInv;
    int t = threadIdx.x;
    for (int i = t; i < 400; i += 256) sW1[i] = W1[i];
    for (int i = t; i < 800; i += 256) sW2[i] = W2[i];
    if (t < 80) sb1[t] = b1[t];
    if (t < 10) { sb2[t] = b2[t]; sW3[t] = W3[t]; }
    if (t == 0) {
        sB3 = b3[0];
        float mn = fdec(g_mn), mx = fdec(g_mx);
        sMn = mn; sInv = 1.f / (mx - mn);
    }
    __syncthreads();
    int r = blockIdx.x * blockDim.x + t;
    if (r >= MM) return;
    float bp[5];
#pragma unroll
    for (int k = 0; k < 5; k++) bp[k] = (g_bp[5 * r + k] - sMn) * sInv;
    float acc[10];
#pragma unroll
    for (int q = 0; q < 10; q++) acc[q] = sb2[q];
    for (int j = 0; j < 80; j++) {
        float s = sb1[j];
#pragma unroll
        for (int k = 0; k < 5; k++) s = fmaf(bp[k], sW1[k * 80 + j], s);
        s = fmaxf(s, 0.f);
#pragma unroll
        for (int q = 0; q < 10; q++) acc[q] = fmaf(s, sW2[j * 10 + q], acc[q]);
    }
    float o = sB3;
#pragma unroll
    for (int q = 0; q < 10; q++) o = fmaf(fmaxf(acc[q], 0.f), sW3[q], o);
    out[r] = 1.f / (1.f + expf(-o));
}

extern "C" void kernel_launch(void* const* d_in, const int* in_sizes, int n_in,
                              void* d_out, int out_size) {
    const int*   ei     = (const int*)d_in[0];     // batch1_edge_index [2,E]
    const float* x      = (const float*)d_in[1];   // batch1_x [N,100]
    const float* transE = (const float*)d_in[4];
    const float* complE = (const float*)d_in[5];
    const float* path   = (const float*)d_in[6];
    const float* ghW1 = (const float*)d_in[8];
    const float* ghb1 = (const float*)d_in[9];
    const float* ghW2 = (const float*)d_in[10];
    const float* ghb2 = (const float*)d_in[11];
    const float* mW1 = (const float*)d_in[16];
    const float* mb1 = (const float*)d_in[17];
    const float* mW2 = (const float*)d_in[18];
    const float* mb2 = (const float*)d_in[19];
    const float* mW3 = (const float*)d_in[20];
    const float* mb3 = (const float*)d_in[21];

    const int* src = ei;
    const int* dst = ei + NE;
    float* out = (float*)d_out;

    k_zero <<<3125, 256>>>();
    k_deg  <<<NE / 1024, 256>>>(dst);               // 4 edges/thread
    k_dinv <<<(NN + 255) / 256, 256>>>();
    k_gemm1<<<NN / 64, 64>>>(x, ghW1);
    k_edge <<<NE / 512, 512>>>(src, dst);           // 1 edge/thread, 4-lane coop
    k_l1fin<<<(NN + 255) / 256, 256>>>(ghb1, ghW2);
    k_edge2<<<FCAP / 256, 256>>>();
    k_samp <<<(MM + 255) / 256, 256>>>(ghb2, transE, complE, path);
    k_mlp  <<<(MM + 255) / 256, 256>>>(mW1, mb1, mW2, mb2, mW3, mb3, out);
}